// round 16
// baseline (speedup 1.0000x reference)
#include <cuda_runtime.h>
#include <cstdint>

#define T_ 64
#define B_ 8
#define S_ 512
#define H_ 512
#define TBH (T_*B_*H_)
#define BSH (B_*S_*H_)

// Scratch (no device allocations allowed).
__device__ float g_enc[BSH];             // enc' = tanh(enc + cov*wcov), rows b*S+s
__device__ float g_a1 [TBH];             // dec@Wq + bq, rows r=t*B+b
__device__ float g_a2 [BSH];             // enc'@Wc, rows b*S+s
__device__ float g_c  [TBH];             // c = align@enc', rows r=t*B+b

__device__ __forceinline__ float ex2f_(float x){ float y; asm("ex2.approx.f32 %0, %1;" : "=f"(y) : "f"(x)); return y; }
__device__ __forceinline__ float rcpf_(float x){ float y; asm("rcp.approx.f32 %0, %1;" : "=f"(y) : "f"(x)); return y; }
__device__ __forceinline__ float tanhf_hw(float x){ float y; asm("tanh.approx.f32 %0, %1;" : "=f"(y) : "f"(x)); return y; }

__device__ __forceinline__ float fast_tanh(float x){
    x = fminf(fmaxf(x, -15.0f), 15.0f);
    float e = ex2f_(x * 2.8853900817779268f);
    return (e - 1.0f) * rcpf_(e + 1.0f);
}

// ---- packed f32x2 helpers ----
__device__ __forceinline__ void ffma2(uint64_t& d, uint64_t a, uint64_t b){
    asm("fma.rn.f32x2 %0, %1, %2, %0;" : "+l"(d) : "l"(a), "l"(b));
}
__device__ __forceinline__ uint64_t pk2dup(float a){
    uint64_t r; asm("mov.b64 %0, {%1, %1};" : "=l"(r) : "f"(a)); return r;
}
__device__ __forceinline__ float2 upk2(uint64_t p){
    float2 f; asm("mov.b64 {%0, %1}, %2;" : "=f"(f.x), "=f"(f.y) : "l"(p)); return f;
}
__device__ __forceinline__ void red_add_v4(float* p, float4 v){
    asm volatile("red.global.add.v4.f32 [%0], {%1, %2, %3, %4};"
                 :: "l"(p), "f"(v.x), "f"(v.y), "f"(v.z), "f"(v.w) : "memory");
}

// -------- 128x128x8 f32x2 body; optional fused tanh on A, optional A store --------
template<bool TANHA, bool STOREA>
__device__ __forceinline__ void gemm128_body(
    const float* __restrict__ Aptr, float* __restrict__ Aout,
    const float* __restrict__ B,
    float* __restrict__ C, const float* __restrict__ bias,
    const float* __restrict__ wcov, float cv,
    int rowBase, int colBase)
{
    __shared__ float As[2][8][128];
    __shared__ float Bs[2][8][128];

    const int tid = threadIdx.x;
    const int tx = tid & 15, ty = tid >> 4;
    const int aRow = tid >> 1,  aCol = (tid & 1) << 2;
    const int bRow = tid >> 5,  bCol = (tid & 31) << 2;

    const float* Bptr = B + (long)bRow*H_ + colBase + bCol;

    uint64_t acc[8][4];
    #pragma unroll
    for (int i = 0; i < 8; i++)
        #pragma unroll
        for (int j = 0; j < 4; j++) acc[i][j] = 0ull;

    float4 av = *(const float4*)(Aptr);
    float4 wv = TANHA ? *(const float4*)(wcov + aCol) : make_float4(0,0,0,0);
    {
        if (TANHA) {
            av.x = fast_tanh(fmaf(cv, wv.x, av.x));
            av.y = fast_tanh(fmaf(cv, wv.y, av.y));
            av.z = fast_tanh(fmaf(cv, wv.z, av.z));
            av.w = fast_tanh(fmaf(cv, wv.w, av.w));
        }
        if (STOREA) *(float4*)(Aout) = av;
        As[0][aCol+0][aRow] = av.x; As[0][aCol+1][aRow] = av.y;
        As[0][aCol+2][aRow] = av.z; As[0][aCol+3][aRow] = av.w;
        *(float4*)(&Bs[0][bRow][bCol]) = *(const float4*)(Bptr);
    }
    __syncthreads();

    const int KT = H_ >> 3;    // 64
    for (int kt = 0; kt < KT; kt++) {
        const int cur = kt & 1;
        float4 bv;
        const bool more = (kt + 1 < KT);
        if (more) {
            av = *(const float4*)(Aptr + (kt+1)*8);
            if (TANHA) wv = *(const float4*)(wcov + (kt+1)*8 + aCol);
            bv = *(const float4*)(Bptr + (long)(kt+1)*8*H_);
        }
        #pragma unroll
        for (int k = 0; k < 8; k++) {
            float4 a0 = *(const float4*)(&As[cur][k][ty << 2]);
            float4 a1 = *(const float4*)(&As[cur][k][(ty << 2) + 64]);
            ulonglong2 bb0 = *(const ulonglong2*)(&Bs[cur][k][tx << 2]);
            ulonglong2 bb1 = *(const ulonglong2*)(&Bs[cur][k][(tx << 2) + 64]);
            uint64_t br[4] = {bb0.x, bb0.y, bb1.x, bb1.y};
            uint64_t pr[8] = {pk2dup(a0.x), pk2dup(a0.y), pk2dup(a0.z), pk2dup(a0.w),
                              pk2dup(a1.x), pk2dup(a1.y), pk2dup(a1.z), pk2dup(a1.w)};
            #pragma unroll
            for (int i = 0; i < 8; i++)
                #pragma unroll
                for (int j = 0; j < 4; j++)
                    ffma2(acc[i][j], pr[i], br[j]);
        }
        if (more) {
            const int nxt = cur ^ 1;
            if (TANHA) {
                av.x = fast_tanh(fmaf(cv, wv.x, av.x));
                av.y = fast_tanh(fmaf(cv, wv.y, av.y));
                av.z = fast_tanh(fmaf(cv, wv.z, av.z));
                av.w = fast_tanh(fmaf(cv, wv.w, av.w));
            }
            if (STOREA) *(float4*)(Aout + (kt+1)*8) = av;
            As[nxt][aCol+0][aRow] = av.x; As[nxt][aCol+1][aRow] = av.y;
            As[nxt][aCol+2][aRow] = av.z; As[nxt][aCol+3][aRow] = av.w;
            *(float4*)(&Bs[nxt][bRow][bCol]) = bv;
        }
        __syncthreads();
    }

    #pragma unroll
    for (int ih = 0; ih < 2; ih++) {
        #pragma unroll
        for (int i = 0; i < 4; i++) {
            int r = rowBase + ih*64 + (ty << 2) + i;
            #pragma unroll
            for (int jh = 0; jh < 2; jh++) {
                float2 p0 = upk2(acc[ih*4+i][jh*2+0]);
                float2 p1 = upk2(acc[ih*4+i][jh*2+1]);
                float4 o = make_float4(p0.x, p0.y, p1.x, p1.y);
                int col = colBase + jh*64 + (tx << 2);
                if (bias) {
                    float4 bvv = *(const float4*)(bias + col);
                    o.x += bvv.x; o.y += bvv.y; o.z += bvv.z; o.w += bvv.w;
                }
                *(float4*)(C + (long)r*H_ + col) = o;
            }
        }
    }
}

// blocks 0..127: a2 = tanh(enc+cov*wcov)@Wc (colBase==0 blocks also store enc'),
// blocks 128..143: a1 = dec@Wq + bq
__global__ __launch_bounds__(256)
void qc_gemm_kernel(const float* __restrict__ enc, const float* __restrict__ cov,
                    const float* __restrict__ wcov, const float* __restrict__ Wc,
                    const float* __restrict__ dec, const float* __restrict__ Wq,
                    const float* __restrict__ bq)
{
    int id = blockIdx.x;
    const int aCol = (threadIdx.x & 1) << 2;
    if (id < 128) {
        int rowBase = (id >> 2)*128, colBase = (id & 3)*128;
        int r = rowBase + (threadIdx.x >> 1);
        int b = r >> 9, s = r & 511;
        const float* Aptr = enc + ((long)s*B_ + b)*H_ + aCol;   // raw enc [s][b][h]
        float cv = cov[b*S_ + s];
        float* Aout = g_enc + (long)r*H_ + aCol;                 // enc' [b][s][h]
        if (colBase == 0)
            gemm128_body<true, true >(Aptr, Aout, Wc, g_a2, nullptr, wcov, cv, rowBase, colBase);
        else
            gemm128_body<true, false>(Aptr, nullptr, Wc, g_a2, nullptr, wcov, cv, rowBase, colBase);
    } else {
        int j = id - 128;
        int rowBase = (j >> 2)*128, colBase = (j & 3)*128;
        const float* Aptr = dec + (long)(rowBase + (threadIdx.x >> 1))*H_ + aCol;
        gemm128_body<false, false>(Aptr, nullptr, Wq, g_a1, bq, nullptr, 0.0f, rowBase, colBase);
    }
}

// -------- 64x64 split-K tile (K=128), double-buffered, f32x2; RED epilogue --------
__device__ __forceinline__ void tile64_red(
    const float* __restrict__ A, long ldaRow,
    const float* __restrict__ Bm, long ldbRow,
    float* __restrict__ C, long ldcRow)
{
    __shared__ float As[2][16][64];
    __shared__ float Bs[2][16][64];

    const int tid = threadIdx.x;
    const int tx = tid & 15, ty = tid >> 4;
    const int aRow = tid >> 2, aCol = (tid & 3) << 2;
    const int bRow = tid >> 4, bCol = (tid & 15) << 2;

    uint64_t acc[4][2];
    #pragma unroll
    for (int i = 0; i < 4; i++) { acc[i][0] = 0ull; acc[i][1] = 0ull; }

    float4 av = *(const float4*)(A + (long)aRow*ldaRow + aCol);
    float4 bv = *(const float4*)(Bm + (long)bRow*ldbRow + bCol);
    int buf = 0;

    for (int k0 = 0; k0 < 128; k0 += 16) {
        As[buf][aCol+0][aRow] = av.x;
        As[buf][aCol+1][aRow] = av.y;
        As[buf][aCol+2][aRow] = av.z;
        As[buf][aCol+3][aRow] = av.w;
        *(float4*)(&Bs[buf][bRow][bCol]) = bv;
        __syncthreads();

        if (k0 + 16 < 128) {
            av = *(const float4*)(A + (long)aRow*ldaRow + k0 + 16 + aCol);
            bv = *(const float4*)(Bm + (long)(k0 + 16 + bRow)*ldbRow + bCol);
        }

        #pragma unroll
        for (int k = 0; k < 16; k++) {
            float4 a = *(const float4*)(&As[buf][k][ty << 2]);
            ulonglong2 bb = *(const ulonglong2*)(&Bs[buf][k][tx << 2]);
            uint64_t pr[4] = {pk2dup(a.x), pk2dup(a.y), pk2dup(a.z), pk2dup(a.w)};
            #pragma unroll
            for (int i = 0; i < 4; i++) {
                ffma2(acc[i][0], pr[i], bb.x);
                ffma2(acc[i][1], pr[i], bb.y);
            }
        }
        __syncthreads();
        buf ^= 1;
    }

    #pragma unroll
    for (int i = 0; i < 4; i++) {
        float2 p0 = upk2(acc[i][0]);
        float2 p1 = upk2(acc[i][1]);
        float4 o = make_float4(p0.x, p0.y, p1.x, p1.y);
        red_add_v4(C + (long)((ty << 2) + i)*ldcRow + (tx << 2), o);
    }
}

// attn_h pre-fill with bias
__global__ void bias_fill_kernel(float* __restrict__ attn_h,
                                 const float* __restrict__ bo)
{
    int idx = (blockIdx.x * 256 + threadIdx.x) * 4;
    *(float4*)(attn_h + idx) = *(const float4*)(bo + (idx & (H_-1)));
}

// out: grid (8 nT, 8 mT, 8 kz). kz 0..3: A = g_c; kz 4..7: A = dec. RED into attn_h.
__global__ __launch_bounds__(256)
void out_red_kernel(const float* __restrict__ dec, const float* __restrict__ Wo,
                    float* __restrict__ attn_h)
{
    const int nT = blockIdx.x, mT = blockIdx.y, kz = blockIdx.z;
    const float* A = (kz < 4) ? (g_c + kz*128) : (dec + (kz-4)*128);
    A += (long)mT*64*H_;
    const float* Bm = Wo + (long)(kz*128)*H_ + nT*64;
    float* C = attn_h + (long)mT*64*H_ + nT*64;
    tile64_red(A, (long)H_, Bm, (long)H_, C, (long)H_);
}

// -------- scores + softmax + fused c, 4 t-rows per block, 2 blocks/SM --------
__global__ __launch_bounds__(512, 2)
void scores_softmax_kernel(const float* __restrict__ v,
                           float* __restrict__ align_out)
{
    const int tg = blockIdx.x;
    const int b  = blockIdx.y;
    const int tid = threadIdx.x;
    const int warp = tid >> 5, lane = tid & 31;

    __shared__ float sa1[4][H_];
    __shared__ float ssc[4][S_];
    __shared__ float sv[H_];
    __shared__ float sred[17];

    #pragma unroll
    for (int i = 0; i < 4; i++)
        sa1[i][tid] = g_a1[((tg*4 + i)*B_ + b)*H_ + tid];
    sv[tid] = v[tid];
    __syncthreads();

    const float* a2base = g_a2 + (long)b*S_*H_ + lane*4;

    float4 x[4];
    {
        const float* p = a2base + (long)warp*H_;
        x[0] = *(const float4*)(p);
        x[1] = *(const float4*)(p + 128);
        x[2] = *(const float4*)(p + 256);
        x[3] = *(const float4*)(p + 384);
    }

    for (int s = warp; s < S_; s += 16) {
        float4 y[4];
        const int sn = s + 16;
        if (sn < S_) {
            const float* p = a2base + (long)sn*H_;
            y[0] = *(const float4*)(p);
            y[1] = *(const float4*)(p + 128);
            y[2] = *(const float4*)(p + 256);
            y[3] = *(const float4*)(p + 384);
        }

        #pragma unroll
        for (int i = 0; i < 4; i++) {
            float4 a0 = *(const float4*)(&sa1[i][lane*4]);
            float4 a1 = *(const float4*)(&sa1[i][lane*4 + 128]);
            float4 a2 = *(const float4*)(&sa1[i][lane*4 + 256]);
            float4 a3 = *(const float4*)(&sa1[i][lane*4 + 384]);
            float4 v0 = *(const float4*)(&sv[lane*4]);
            float4 v1 = *(const float4*)(&sv[lane*4 + 128]);
            float4 v2 = *(const float4*)(&sv[lane*4 + 256]);
            float4 v3 = *(const float4*)(&sv[lane*4 + 384]);
            float acc = 0.0f;
            acc = fmaf(tanhf_hw(a0.x + x[0].x), v0.x, acc);
            acc = fmaf(tanhf_hw(a0.y + x[0].y), v0.y, acc);
            acc = fmaf(tanhf_hw(a0.z + x[0].z), v0.z, acc);
            acc = fmaf(tanhf_hw(a0.w + x[0].w), v0.w, acc);
            acc = fmaf(tanhf_hw(a1.x + x[1].x), v1.x, acc);
            acc = fmaf(tanhf_hw(a1.y + x[1].y), v1.y, acc);
            acc = fmaf(tanhf_hw(a1.z + x[1].z), v1.z, acc);
            acc = fmaf(tanhf_hw(a1.w + x[1].w), v1.w, acc);
            acc = fmaf(tanhf_hw(a2.x + x[2].x), v2.x, acc);
            acc = fmaf(tanhf_hw(a2.y + x[2].y), v2.y, acc);
            acc = fmaf(tanhf_hw(a2.z + x[2].z), v2.z, acc);
            acc = fmaf(tanhf_hw(a2.w + x[2].w), v2.w, acc);
            acc = fmaf(tanhf_hw(a3.x + x[3].x), v3.x, acc);
            acc = fmaf(tanhf_hw(a3.y + x[3].y), v3.y, acc);
            acc = fmaf(tanhf_hw(a3.z + x[3].z), v3.z, acc);
            acc = fmaf(tanhf_hw(a3.w + x[3].w), v3.w, acc);
            #pragma unroll
            for (int o = 16; o > 0; o >>= 1)
                acc += __shfl_xor_sync(0xffffffffu, acc, o);
            if (lane == 0) ssc[i][s] = acc;
        }
        x[0] = y[0]; x[1] = y[1]; x[2] = y[2]; x[3] = y[3];
    }
    __syncthreads();

    // softmax per row; probs written to output AND kept in ssc for the c-phase
    #pragma unroll
    for (int i = 0; i < 4; i++) {
        float xx = ssc[i][tid];
        float m = xx;
        #pragma unroll
        for (int o = 16; o > 0; o >>= 1) m = fmaxf(m, __shfl_xor_sync(0xffffffffu, m, o));
        if (lane == 0) sred[warp] = m;
        __syncthreads();
        if (warp == 0) {
            float mm = (lane < 16) ? sred[lane] : -1e30f;
            #pragma unroll
            for (int o = 8; o > 0; o >>= 1) mm = fmaxf(mm, __shfl_xor_sync(0xffffffffu, mm, o));
            if (lane == 0) sred[16] = mm;
        }
        __syncthreads();
        const float mx = sred[16];
        float e = ex2f_((xx - mx) * 1.4426950408889634f);
        float ssum = e;
        #pragma unroll
        for (int o = 16; o > 0; o >>= 1) ssum += __shfl_xor_sync(0xffffffffu, ssum, o);
        __syncthreads();
        if (lane == 0) sred[warp] = ssum;
        __syncthreads();
        if (warp == 0) {
            float t = (lane < 16) ? sred[lane] : 0.0f;
            #pragma unroll
            for (int o = 8; o > 0; o >>= 1) t += __shfl_xor_sync(0xffffffffu, t, o);
            if (lane == 0) sred[16] = t;
        }
        __syncthreads();
        float p = e * rcpf_(sred[16]);
        ssc[i][tid] = p;                                   // keep for c-phase
        align_out[(long)((tg*4 + i)*B_ + b)*S_ + tid] = p;
        __syncthreads();
    }

    // ---- fused c: c[i][h] = sum_s p[i][s] * enc'[b][s][h] ----
    {
        const int hq = warp & 3, sq = warp >> 2;
        const int h0 = hq*128 + lane*4;
        uint64_t acc2[4][2];
        for (int i = 0; i < 4; i++) { acc2[i][0] = 0ull; acc2[i][1] = 0ull; }

        const float* ebase = g_enc + ((long)b*S_ + sq*128)*H_ + h0;
        for (int s = 0; s < 128; s++) {
            ulonglong2 ev = *(const ulonglong2*)(ebase + (long)s*H_);
            #pragma unroll
            for (int i = 0; i < 4; i++) {
                uint64_t pd = pk2dup(ssc[i][sq*128 + s]);
                ffma2(acc2[i][0], pd, ev.x);
                ffma2(acc2[i][1], pd, ev.y);
            }
        }
        float4 facc[4];
        for (int i = 0; i < 4; i++) {
            float2 p0 = upk2(acc2[i][0]);
            float2 p1 = upk2(acc2[i][1]);
            facc[i] = make_float4(p0.x, p0.y, p1.x, p1.y);
        }
        __syncthreads();

        if (sq == 1) {
            for (int i = 0; i < 4; i++) *(float4*)(&sa1[i][h0]) = facc[i];
        }
        if (sq == 3) {
            for (int i = 0; i < 4; i++) *(float4*)(&ssc[i][h0]) = facc[i];
        }
        __syncthreads();
        if (sq == 0) {
            for (int i = 0; i < 4; i++) {
                float4 t = *(const float4*)(&sa1[i][h0]);
                facc[i].x += t.x; facc[i].y += t.y; facc[i].z += t.z; facc[i].w += t.w;
            }
        }
        if (sq == 2) {
            for (int i = 0; i < 4; i++) {
                float4 t = *(const float4*)(&ssc[i][h0]);
                facc[i].x += t.x; facc[i].y += t.y; facc[i].z += t.z; facc[i].w += t.w;
            }
        }
        __syncthreads();
        if (sq == 2) {
            for (int i = 0; i < 4; i++) *(float4*)(&sa1[i][h0]) = facc[i];
        }
        __syncthreads();
        if (sq == 0) {
            for (int i = 0; i < 4; i++) {
                float4 t = *(const float4*)(&sa1[i][h0]);
                facc[i].x += t.x; facc[i].y += t.y; facc[i].z += t.z; facc[i].w += t.w;
                *(float4*)(g_c + ((long)((tg*4 + i)*B_ + b))*H_ + h0) = facc[i];
            }
        }
    }
}

extern "C" void kernel_launch(void* const* d_in, const int* in_sizes, int n_in,
                              void* d_out, int out_size)
{
    const float* dec  = (const float*)d_in[0];
    const float* enc  = (const float*)d_in[1];
    const float* cov  = (const float*)d_in[2];
    const float* Wq   = (const float*)d_in[3];
    const float* bq   = (const float*)d_in[4];
    const float* Wc   = (const float*)d_in[5];
    const float* v    = (const float*)d_in[6];
    const float* Wo   = (const float*)d_in[7];
    const float* bo   = (const float*)d_in[8];
    const float* wcov = (const float*)d_in[9];

    float* attn_h = (float*)d_out;
    float* align  = (float*)d_out + TBH;

    // 1) pre-fill attn_h with bias (RED targets must start initialized)
    bias_fill_kernel<<<TBH/1024, 256>>>(attn_h, bo);

    // 2) a1 + a2 (and enc' store) in one 144-block wave
    qc_gemm_kernel<<<144, 256>>>(enc, cov, wcov, Wc, dec, Wq, bq);

    // 3) scores + softmax + fused c (2 blocks/SM)
    scores_softmax_kernel<<<dim3(16, 8), 512>>>(v, align);

    // 4) out: c@Wo1 + dec@Wo2, RED-accumulate into attn_h (512 blocks)
    out_red_kernel<<<dim3(8, 8, 8), 256>>>(dec, Wo, attn_h);
}

// round 17
// speedup vs baseline: 1.1112x; 1.1112x over previous
#include <cuda_runtime.h>
#include <cstdint>

#define T_ 64
#define B_ 8
#define S_ 512
#define H_ 512
#define TBH (T_*B_*H_)
#define BSH (B_*S_*H_)

// Scratch (no device allocations allowed).
__device__ float g_enc[BSH];             // enc' = tanh(enc + cov*wcov), rows b*S+s
__device__ float g_a1 [TBH];             // dec@Wq + bq, rows r=t*B+b
__device__ float g_a2 [BSH];             // enc'@Wc, rows b*S+s
__device__ float g_c  [TBH];             // c = align@enc', rows r=t*B+b

__device__ __forceinline__ float ex2f_(float x){ float y; asm("ex2.approx.f32 %0, %1;" : "=f"(y) : "f"(x)); return y; }
__device__ __forceinline__ float rcpf_(float x){ float y; asm("rcp.approx.f32 %0, %1;" : "=f"(y) : "f"(x)); return y; }
__device__ __forceinline__ float tanhf_hw(float x){ float y; asm("tanh.approx.f32 %0, %1;" : "=f"(y) : "f"(x)); return y; }

__device__ __forceinline__ float fast_tanh(float x){
    x = fminf(fmaxf(x, -15.0f), 15.0f);
    float e = ex2f_(x * 2.8853900817779268f);
    return (e - 1.0f) * rcpf_(e + 1.0f);
}

// ---- packed f32x2 helpers ----
__device__ __forceinline__ void ffma2(uint64_t& d, uint64_t a, uint64_t b){
    asm("fma.rn.f32x2 %0, %1, %2, %0;" : "+l"(d) : "l"(a), "l"(b));
}
__device__ __forceinline__ uint64_t pk2dup(float a){
    uint64_t r; asm("mov.b64 %0, {%1, %1};" : "=l"(r) : "f"(a)); return r;
}
__device__ __forceinline__ float2 upk2(uint64_t p){
    float2 f; asm("mov.b64 {%0, %1}, %2;" : "=f"(f.x), "=f"(f.y) : "l"(p)); return f;
}
__device__ __forceinline__ void red_add_v4(float* p, float4 v){
    asm volatile("red.global.add.v4.f32 [%0], {%1, %2, %3, %4};"
                 :: "l"(p), "f"(v.x), "f"(v.y), "f"(v.z), "f"(v.w) : "memory");
}

// -------- 128x128xK f32x2 body; tanh/A-store options, STG or RED epilogue --------
template<int KELEMS, bool TANHA, bool STOREA, bool REDC>
__device__ __forceinline__ void gemm128_body(
    const float* __restrict__ Aptr, float* __restrict__ Aout,
    const float* __restrict__ Bptr0,      // already offset to (k0, colBase+bCol)
    float* __restrict__ C, const float* __restrict__ bias,
    const float* __restrict__ wcov, float cv,
    int rowBase, int colBase)
{
    __shared__ float As[2][8][128];
    __shared__ float Bs[2][8][128];

    const int tid = threadIdx.x;
    const int tx = tid & 15, ty = tid >> 4;
    const int aRow = tid >> 1,  aCol = (tid & 1) << 2;
    const int bRow = tid >> 5,  bCol = (tid & 31) << 2;
    (void)bRow; (void)bCol;

    uint64_t acc[8][4];
    #pragma unroll
    for (int i = 0; i < 8; i++)
        #pragma unroll
        for (int j = 0; j < 4; j++) acc[i][j] = 0ull;

    float4 av = *(const float4*)(Aptr);
    float4 wv = TANHA ? *(const float4*)(wcov + aCol) : make_float4(0,0,0,0);
    {
        if (TANHA) {
            av.x = fast_tanh(fmaf(cv, wv.x, av.x));
            av.y = fast_tanh(fmaf(cv, wv.y, av.y));
            av.z = fast_tanh(fmaf(cv, wv.z, av.z));
            av.w = fast_tanh(fmaf(cv, wv.w, av.w));
        }
        if (STOREA) *(float4*)(Aout) = av;
        As[0][aCol+0][aRow] = av.x; As[0][aCol+1][aRow] = av.y;
        As[0][aCol+2][aRow] = av.z; As[0][aCol+3][aRow] = av.w;
        *(float4*)(&Bs[0][tid >> 5][(tid & 31) << 2]) = *(const float4*)(Bptr0);
    }
    __syncthreads();

    const int KT = KELEMS >> 3;
    for (int kt = 0; kt < KT; kt++) {
        const int cur = kt & 1;
        float4 bv;
        const bool more = (kt + 1 < KT);
        if (more) {
            av = *(const float4*)(Aptr + (kt+1)*8);
            if (TANHA) wv = *(const float4*)(wcov + (kt+1)*8 + aCol);
            bv = *(const float4*)(Bptr0 + (long)(kt+1)*8*H_);
        }
        #pragma unroll
        for (int k = 0; k < 8; k++) {
            float4 a0 = *(const float4*)(&As[cur][k][ty << 2]);
            float4 a1 = *(const float4*)(&As[cur][k][(ty << 2) + 64]);
            ulonglong2 bb0 = *(const ulonglong2*)(&Bs[cur][k][tx << 2]);
            ulonglong2 bb1 = *(const ulonglong2*)(&Bs[cur][k][(tx << 2) + 64]);
            uint64_t br[4] = {bb0.x, bb0.y, bb1.x, bb1.y};
            uint64_t pr[8] = {pk2dup(a0.x), pk2dup(a0.y), pk2dup(a0.z), pk2dup(a0.w),
                              pk2dup(a1.x), pk2dup(a1.y), pk2dup(a1.z), pk2dup(a1.w)};
            #pragma unroll
            for (int i = 0; i < 8; i++)
                #pragma unroll
                for (int j = 0; j < 4; j++)
                    ffma2(acc[i][j], pr[i], br[j]);
        }
        if (more) {
            const int nxt = cur ^ 1;
            if (TANHA) {
                av.x = fast_tanh(fmaf(cv, wv.x, av.x));
                av.y = fast_tanh(fmaf(cv, wv.y, av.y));
                av.z = fast_tanh(fmaf(cv, wv.z, av.z));
                av.w = fast_tanh(fmaf(cv, wv.w, av.w));
            }
            if (STOREA) *(float4*)(Aout + (kt+1)*8) = av;
            As[nxt][aCol+0][aRow] = av.x; As[nxt][aCol+1][aRow] = av.y;
            As[nxt][aCol+2][aRow] = av.z; As[nxt][aCol+3][aRow] = av.w;
            *(float4*)(&Bs[nxt][tid >> 5][(tid & 31) << 2]) = bv;
        }
        __syncthreads();
    }

    #pragma unroll
    for (int ih = 0; ih < 2; ih++) {
        #pragma unroll
        for (int i = 0; i < 4; i++) {
            int r = rowBase + ih*64 + (ty << 2) + i;
            #pragma unroll
            for (int jh = 0; jh < 2; jh++) {
                float2 p0 = upk2(acc[ih*4+i][jh*2+0]);
                float2 p1 = upk2(acc[ih*4+i][jh*2+1]);
                float4 o = make_float4(p0.x, p0.y, p1.x, p1.y);
                int col = colBase + jh*64 + (tx << 2);
                if (bias) {
                    float4 bvv = *(const float4*)(bias + col);
                    o.x += bvv.x; o.y += bvv.y; o.z += bvv.z; o.w += bvv.w;
                }
                if (REDC) red_add_v4(C + (long)r*H_ + col, o);
                else      *(float4*)(C + (long)r*H_ + col) = o;
            }
        }
    }
}

// blocks 0..127: a2 = tanh(enc+cov*wcov)@Wc (colBase==0 blocks also store enc'),
// blocks 128..143: a1 = dec@Wq + bq
__global__ __launch_bounds__(256)
void qc_gemm_kernel(const float* __restrict__ enc, const float* __restrict__ cov,
                    const float* __restrict__ wcov, const float* __restrict__ Wc,
                    const float* __restrict__ dec, const float* __restrict__ Wq,
                    const float* __restrict__ bq)
{
    int id = blockIdx.x;
    const int tid = threadIdx.x;
    const int aCol = (tid & 1) << 2;
    const int bRow = tid >> 5, bCol = (tid & 31) << 2;
    if (id < 128) {
        int rowBase = (id >> 2)*128, colBase = (id & 3)*128;
        int r = rowBase + (tid >> 1);
        int b = r >> 9, s = r & 511;
        const float* Aptr = enc + ((long)s*B_ + b)*H_ + aCol;
        const float* Bptr = Wc + (long)bRow*H_ + colBase + bCol;
        float cv = cov[b*S_ + s];
        float* Aout = g_enc + (long)r*H_ + aCol;
        if (colBase == 0)
            gemm128_body<512, true, true, false>(Aptr, Aout, Bptr, g_a2, nullptr, wcov, cv, rowBase, colBase);
        else
            gemm128_body<512, true, false, false>(Aptr, nullptr, Bptr, g_a2, nullptr, wcov, cv, rowBase, colBase);
    } else {
        int j = id - 128;
        int rowBase = (j >> 2)*128, colBase = (j & 3)*128;
        const float* Aptr = dec + (long)(rowBase + (tid >> 1))*H_ + aCol;
        const float* Bptr = Wq + (long)bRow*H_ + colBase + bCol;
        gemm128_body<512, false, false, false>(Aptr, nullptr, Bptr, g_a1, bq, nullptr, 0.0f, rowBase, colBase);
    }
}

// attn_h pre-fill with bias
__global__ void bias_fill_kernel(float* __restrict__ attn_h,
                                 const float* __restrict__ bo)
{
    int idx = (blockIdx.x * 256 + threadIdx.x) * 4;
    *(float4*)(attn_h + idx) = *(const float4*)(bo + (idx & (H_-1)));
}

// out: grid (4 nT, 4 mT, 8 kz), 128x128 tiles, K=128 chunks, RED into attn_h.
// kz 0..3: A = g_c (cols kz*128..); kz 4..7: A = dec (cols (kz-4)*128..)
__global__ __launch_bounds__(256)
void out_gemm_kernel(const float* __restrict__ dec, const float* __restrict__ Wo,
                     float* __restrict__ attn_h)
{
    const int nT = blockIdx.x, mT = blockIdx.y, kz = blockIdx.z;
    const int tid = threadIdx.x;
    const int aCol = (tid & 1) << 2;
    const int bRow = tid >> 5, bCol = (tid & 31) << 2;
    const int rowBase = mT*128, colBase = nT*128;

    const float* A = (kz < 4) ? (g_c + kz*128) : (dec + (kz-4)*128);
    const float* Aptr = A + (long)(rowBase + (tid >> 1))*H_ + aCol;
    const float* Bptr = Wo + (long)(kz*128 + bRow)*H_ + colBase + bCol;
    gemm128_body<128, false, false, true>(Aptr, nullptr, Bptr, attn_h, nullptr,
                                          nullptr, 0.0f, rowBase, colBase);
}

// -------- scores + softmax + fused c, 4 t-rows per block --------
__global__ __launch_bounds__(512)
void scores_softmax_kernel(const float* __restrict__ v,
                           float* __restrict__ align_out)
{
    const int tg = blockIdx.x;
    const int b  = blockIdx.y;
    const int tid = threadIdx.x;
    const int warp = tid >> 5, lane = tid & 31;

    __shared__ float sa1[4][H_];
    __shared__ float ssc[4][S_];
    __shared__ float sred[17];

    #pragma unroll
    for (int i = 0; i < 4; i++)
        sa1[i][tid] = g_a1[((tg*4 + i)*B_ + b)*H_ + tid];

    float4 v0 = *(const float4*)(v + lane*4);
    float4 v1 = *(const float4*)(v + lane*4 + 128);
    float4 v2 = *(const float4*)(v + lane*4 + 256);
    float4 v3 = *(const float4*)(v + lane*4 + 384);
    __syncthreads();

    const float* a2base = g_a2 + (long)b*S_*H_ + lane*4;

    float4 x[4];
    {
        const float* p = a2base + (long)warp*H_;
        x[0] = *(const float4*)(p);
        x[1] = *(const float4*)(p + 128);
        x[2] = *(const float4*)(p + 256);
        x[3] = *(const float4*)(p + 384);
    }

    for (int s = warp; s < S_; s += 16) {
        float4 y[4];
        const int sn = s + 16;
        if (sn < S_) {
            const float* p = a2base + (long)sn*H_;
            y[0] = *(const float4*)(p);
            y[1] = *(const float4*)(p + 128);
            y[2] = *(const float4*)(p + 256);
            y[3] = *(const float4*)(p + 384);
        }

        #pragma unroll
        for (int i = 0; i < 4; i++) {
            float4 a0 = *(const float4*)(&sa1[i][lane*4]);
            float4 a1 = *(const float4*)(&sa1[i][lane*4 + 128]);
            float4 a2 = *(const float4*)(&sa1[i][lane*4 + 256]);
            float4 a3 = *(const float4*)(&sa1[i][lane*4 + 384]);
            float acc = 0.0f;
            acc = fmaf(tanhf_hw(a0.x + x[0].x), v0.x, acc);
            acc = fmaf(tanhf_hw(a0.y + x[0].y), v0.y, acc);
            acc = fmaf(tanhf_hw(a0.z + x[0].z), v0.z, acc);
            acc = fmaf(tanhf_hw(a0.w + x[0].w), v0.w, acc);
            acc = fmaf(tanhf_hw(a1.x + x[1].x), v1.x, acc);
            acc = fmaf(tanhf_hw(a1.y + x[1].y), v1.y, acc);
            acc = fmaf(tanhf_hw(a1.z + x[1].z), v1.z, acc);
            acc = fmaf(tanhf_hw(a1.w + x[1].w), v1.w, acc);
            acc = fmaf(tanhf_hw(a2.x + x[2].x), v2.x, acc);
            acc = fmaf(tanhf_hw(a2.y + x[2].y), v2.y, acc);
            acc = fmaf(tanhf_hw(a2.z + x[2].z), v2.z, acc);
            acc = fmaf(tanhf_hw(a2.w + x[2].w), v2.w, acc);
            acc = fmaf(tanhf_hw(a3.x + x[3].x), v3.x, acc);
            acc = fmaf(tanhf_hw(a3.y + x[3].y), v3.y, acc);
            acc = fmaf(tanhf_hw(a3.z + x[3].z), v3.z, acc);
            acc = fmaf(tanhf_hw(a3.w + x[3].w), v3.w, acc);
            #pragma unroll
            for (int o = 16; o > 0; o >>= 1)
                acc += __shfl_xor_sync(0xffffffffu, acc, o);
            if (lane == 0) ssc[i][s] = acc;
        }
        x[0] = y[0]; x[1] = y[1]; x[2] = y[2]; x[3] = y[3];
    }
    __syncthreads();

    #pragma unroll
    for (int i = 0; i < 4; i++) {
        float xx = ssc[i][tid];
        float m = xx;
        #pragma unroll
        for (int o = 16; o > 0; o >>= 1) m = fmaxf(m, __shfl_xor_sync(0xffffffffu, m, o));
        if (lane == 0) sred[warp] = m;
        __syncthreads();
        if (warp == 0) {
            float mm = (lane < 16) ? sred[lane] : -1e30f;
            #pragma unroll
            for (int o = 8; o > 0; o >>= 1) mm = fmaxf(mm, __shfl_xor_sync(0xffffffffu, mm, o));
            if (lane == 0) sred[16] = mm;
        }
        __syncthreads();
        const float mx = sred[16];
        float e = ex2f_((xx - mx) * 1.4426950408889634f);
        float ssum = e;
        #pragma unroll
        for (int o = 16; o > 0; o >>= 1) ssum += __shfl_xor_sync(0xffffffffu, ssum, o);
        __syncthreads();
        if (lane == 0) sred[warp] = ssum;
        __syncthreads();
        if (warp == 0) {
            float t = (lane < 16) ? sred[lane] : 0.0f;
            #pragma unroll
            for (int o = 8; o > 0; o >>= 1) t += __shfl_xor_sync(0xffffffffu, t, o);
            if (lane == 0) sred[16] = t;
        }
        __syncthreads();
        float p = e * rcpf_(sred[16]);
        ssc[i][tid] = p;                                   // keep for c-phase
        align_out[(long)((tg*4 + i)*B_ + b)*S_ + tid] = p;
        __syncthreads();
    }

    // ---- fused c: c[i][h] = sum_s p[i][s] * enc'[b][s][h] ----
    {
        const int hq = warp & 3, sq = warp >> 2;
        const int h0 = hq*128 + lane*4;
        uint64_t acc2[4][2];
        for (int i = 0; i < 4; i++) { acc2[i][0] = 0ull; acc2[i][1] = 0ull; }

        const float* ebase = g_enc + ((long)b*S_ + sq*128)*H_ + h0;
        for (int s = 0; s < 128; s++) {
            ulonglong2 ev = *(const ulonglong2*)(ebase + (long)s*H_);
            #pragma unroll
            for (int i = 0; i < 4; i++) {
                uint64_t pd = pk2dup(ssc[i][sq*128 + s]);
                ffma2(acc2[i][0], pd, ev.x);
                ffma2(acc2[i][1], pd, ev.y);
            }
        }
        float4 facc[4];
        for (int i = 0; i < 4; i++) {
            float2 p0 = upk2(acc2[i][0]);
            float2 p1 = upk2(acc2[i][1]);
            facc[i] = make_float4(p0.x, p0.y, p1.x, p1.y);
        }
        __syncthreads();

        if (sq == 1) {
            for (int i = 0; i < 4; i++) *(float4*)(&sa1[i][h0]) = facc[i];
        }
        if (sq == 3) {
            for (int i = 0; i < 4; i++) *(float4*)(&ssc[i][h0]) = facc[i];
        }
        __syncthreads();
        if (sq == 0) {
            for (int i = 0; i < 4; i++) {
                float4 t = *(const float4*)(&sa1[i][h0]);
                facc[i].x += t.x; facc[i].y += t.y; facc[i].z += t.z; facc[i].w += t.w;
            }
        }
        if (sq == 2) {
            for (int i = 0; i < 4; i++) {
                float4 t = *(const float4*)(&ssc[i][h0]);
                facc[i].x += t.x; facc[i].y += t.y; facc[i].z += t.z; facc[i].w += t.w;
            }
        }
        __syncthreads();
        if (sq == 2) {
            for (int i = 0; i < 4; i++) *(float4*)(&sa1[i][h0]) = facc[i];
        }
        __syncthreads();
        if (sq == 0) {
            for (int i = 0; i < 4; i++) {
                float4 t = *(const float4*)(&sa1[i][h0]);
                facc[i].x += t.x; facc[i].y += t.y; facc[i].z += t.z; facc[i].w += t.w;
                *(float4*)(g_c + ((long)((tg*4 + i)*B_ + b))*H_ + h0) = facc[i];
            }
        }
    }
}

extern "C" void kernel_launch(void* const* d_in, const int* in_sizes, int n_in,
                              void* d_out, int out_size)
{
    const float* dec  = (const float*)d_in[0];
    const float* enc  = (const float*)d_in[1];
    const float* cov  = (const float*)d_in[2];
    const float* Wq   = (const float*)d_in[3];
    const float* bq   = (const float*)d_in[4];
    const float* Wc   = (const float*)d_in[5];
    const float* v    = (const float*)d_in[6];
    const float* Wo   = (const float*)d_in[7];
    const float* bo   = (const float*)d_in[8];
    const float* wcov = (const float*)d_in[9];

    float* attn_h = (float*)d_out;
    float* align  = (float*)d_out + TBH;

    // 1) pre-fill attn_h with bias (RED targets must start initialized)
    bias_fill_kernel<<<TBH/1024, 256>>>(attn_h, bo);

    // 2) a1 + a2 (and enc' store) in one 144-block wave
    qc_gemm_kernel<<<144, 256>>>(enc, cov, wcov, Wc, dec, Wq, bq);

    // 3) scores + softmax + fused c
    scores_softmax_kernel<<<dim3(16, 8), 512>>>(v, align);

    // 4) out: [c|dec]@Wo via 128x128 body, K=128 chunks, RED into attn_h
    out_gemm_kernel<<<dim3(4, 4, 8), 256>>>(dec, Wo, attn_h);
}